// round 6
// baseline (speedup 1.0000x reference)
#include <cuda_runtime.h>
#include <cstdint>

#define Mm 32
#define Nn 8192
#define Dd 64
#define Kk 16

// Output packing (concatenated in reference-return order):
//   responsibilities [N, M]            offset 0,        262144 floats
//   e_z              [M, N, K]         offset 262144,   4194304 floats
//   e_zz             [M, N, K, K]      offset 4456448,  67108864 floats
#define EZ_OFF  ((size_t)262144)
#define EZZ_OFF ((size_t)4456448)

// Scratch (static device globals; no allocation)
__device__ float g_beta[Mm][Kk][Dd];    // beta = Minv * Lambda^T * Psi^{-1}  [K,D]
__device__ float g_Mmat[Mm][Kk][Kk];    // M = I + Lambda^T Psi^{-1} Lambda
__device__ float g_Minv[Mm][Kk][Kk];    // M^{-1}  (== term1 exactly)
__device__ float g_cst[Mm];             // log(pi+1e-10) - 0.5*(D log 2pi + logdet Sigma)
__device__ float g_logprob[Mm * Nn];    // [M][N]

// ---------------------------------------------------------------------------
// Kernel 1: per-component setup. One warp per component (32 blocks x 32 thr).
// ---------------------------------------------------------------------------
__global__ void setup_kernel(const float* __restrict__ pi,
                             const float* __restrict__ Lambda,   // [M,D,K]
                             const float* __restrict__ Psi) {    // [D]
    const int m = blockIdx.x;
    const int lane = threadIdx.x;

    __shared__ float Ls[Dd][Kk];     // Lambda_m as [d][k]
    __shared__ float ip[Dd];         // 1/(Psi+1e-6)
    __shared__ float Ms[Kk][Kk];     // M
    __shared__ float Ch[Kk][Kk];     // chol(M), lower
    __shared__ float Mi[Kk][Kk];     // M^{-1}

    for (int i = lane; i < Dd * Kk; i += 32)
        Ls[i / Kk][i % Kk] = Lambda[(size_t)m * Dd * Kk + i];
    for (int d = lane; d < Dd; d += 32)
        ip[d] = 1.0f / (Psi[d] + 1e-6f);
    __syncwarp();

    // M = I + Lambda^T Psi^{-1} Lambda   (256 entries over 32 lanes)
    for (int e = lane; e < Kk * Kk; e += 32) {
        const int k1 = e / Kk, k2 = e % Kk;
        float s = (k1 == k2) ? 1.0f : 0.0f;
        #pragma unroll 8
        for (int d = 0; d < Dd; d++) s += Ls[d][k1] * Ls[d][k2] * ip[d];
        Ms[k1][k2] = s;
        g_Mmat[m][k1][k2] = s;
    }
    __syncwarp();

    // Warp-cooperative 16x16 Cholesky (lanes = rows)
    for (int j = 0; j < Kk; j++) {
        float s = 0.0f;
        if (lane >= j && lane < Kk) {
            s = Ms[lane][j];
            for (int k = 0; k < j; k++) s -= Ch[lane][k] * Ch[j][k];
        }
        float diag = __shfl_sync(0xffffffffu, s, j);
        diag = sqrtf(diag);
        if (lane == j) Ch[j][j] = diag;
        else if (lane > j && lane < Kk) Ch[lane][j] = s / diag;
        __syncwarp();
    }

    // Constant: log(pi+1e-10) - 0.5*(D*log(2pi) + logdet Sigma)
    if (lane == 0) {
        float ld = 0.0f;
        #pragma unroll
        for (int j = 0; j < Kk; j++) ld += 2.0f * logf(Ch[j][j]);
        for (int d = 0; d < Dd; d++) ld += logf(Psi[d] + 1e-6f);
        const float log2pi = 1.8378770664093453f;
        g_cst[m] = logf(pi[m] + 1e-10f) - 0.5f * ((float)Dd * log2pi + ld);
    }
    __syncwarp();

    // Invert M via two triangular solves; lane c owns column c
    if (lane < Kk) {
        float w[Kk], z[Kk];
        #pragma unroll
        for (int i = 0; i < Kk; i++) {
            float s = (i == lane) ? 1.0f : 0.0f;
            #pragma unroll
            for (int k = 0; k < Kk; k++) if (k < i) s -= Ch[i][k] * w[k];
            w[i] = s / Ch[i][i];
        }
        #pragma unroll
        for (int i = Kk - 1; i >= 0; i--) {
            float s = w[i];
            #pragma unroll
            for (int k = 0; k < Kk; k++) if (k > i) s -= Ch[k][i] * z[k];
            z[i] = s / Ch[i][i];
        }
        #pragma unroll
        for (int i = 0; i < Kk; i++) {
            Mi[i][lane] = z[i];
            g_Minv[m][i][lane] = z[i];   // term1 == Minv exactly
        }
    }
    __syncwarp();

    // beta[k][d] = (sum_j Minv[k][j] * Lambda[d][j]) * ip[d]
    for (int e = lane; e < Kk * Dd; e += 32) {
        const int k = e / Dd, d = e % Dd;
        float s = 0.0f;
        #pragma unroll
        for (int j = 0; j < Kk; j++) s += Mi[k][j] * Ls[d][j];
        g_beta[m][k][d] = s * ip[d];
    }
}

// ---------------------------------------------------------------------------
// Kernel 2: main E-step. Grid (N/256, M), 256 threads. Thread = one point.
// ---------------------------------------------------------------------------
__global__ __launch_bounds__(256) void main_kernel(const float* __restrict__ X,
                                                   const float* __restrict__ mu,
                                                   const float* __restrict__ Psi,
                                                   float* __restrict__ out) {
    const int m = blockIdx.y;
    const int n0 = blockIdx.x * 256;
    const int tid = threadIdx.x;
    const int n = n0 + tid;
    const int w = tid >> 5, lane = tid & 31;

    __shared__ float beta_s[Kk][Dd];       // 4 KB
    __shared__ float Mm_s[Kk][Kk];         // 1 KB
    __shared__ float Mi_s[Kk][Kk];         // 1 KB
    __shared__ float mu_s[Dd];
    __shared__ float ip_s[Dd];
    __shared__ float ez_s[8][Kk * 33];     // padded stride-33 per warp: ~16.9 KB

    for (int i = tid; i < Kk * Dd; i += 256)
        ((float*)beta_s)[i] = ((const float*)g_beta[m])[i];
    for (int i = tid; i < Kk * Kk; i += 256) {
        ((float*)Mm_s)[i] = ((const float*)g_Mmat[m])[i];
        ((float*)Mi_s)[i] = ((const float*)g_Minv[m])[i];
    }
    if (tid < Dd) {
        mu_s[tid] = mu[m * Dd + tid];
        ip_s[tid] = 1.0f / (Psi[tid] + 1e-6f);
    }
    __syncthreads();

    // ---- e_z = beta * diff ; q = diff^T Psi^{-1} diff ----
    float ez[Kk];
    #pragma unroll
    for (int k = 0; k < Kk; k++) ez[k] = 0.0f;
    float q = 0.0f;

    const float4* xr = (const float4*)(X + (size_t)n * Dd);
    #pragma unroll
    for (int g = 0; g < Dd / 4; g++) {
        const float4 xv = xr[g];
        float4 dv;
        dv.x = xv.x - mu_s[4 * g + 0];
        dv.y = xv.y - mu_s[4 * g + 1];
        dv.z = xv.z - mu_s[4 * g + 2];
        dv.w = xv.w - mu_s[4 * g + 3];
        q += dv.x * dv.x * ip_s[4 * g + 0];
        q += dv.y * dv.y * ip_s[4 * g + 1];
        q += dv.z * dv.z * ip_s[4 * g + 2];
        q += dv.w * dv.w * ip_s[4 * g + 3];
        #pragma unroll
        for (int k = 0; k < Kk; k++) {
            const float4 bv = *(const float4*)&beta_s[k][4 * g];
            ez[k] += dv.x * bv.x + dv.y * bv.y + dv.z * bv.z + dv.w * bv.w;
        }
    }

    // ---- maha = q - ez^T M ez ; log-prob ----
    float quad = 0.0f;
    #pragma unroll
    for (int i = 0; i < Kk; i++) {
        float s = 0.0f;
        #pragma unroll
        for (int j = 0; j < Kk; j++) s += Mm_s[i][j] * ez[j];
        quad += s * ez[i];
    }
    g_logprob[(size_t)m * Nn + n] = g_cst[m] - 0.5f * (q - quad);

    // ---- write e_z directly, streaming (per-thread 64B, warp = 2KB burst) ----
    {
        float4* o = (float4*)(out + EZ_OFF + ((size_t)m * Nn + n) * Kk);
        __stcs(&o[0], make_float4(ez[0], ez[1], ez[2], ez[3]));
        __stcs(&o[1], make_float4(ez[4], ez[5], ez[6], ez[7]));
        __stcs(&o[2], make_float4(ez[8], ez[9], ez[10], ez[11]));
        __stcs(&o[3], make_float4(ez[12], ez[13], ez[14], ez[15]));
    }

    // ---- stage ez into padded smem (transposed) for cooperative e_zz ----
    float* ew = ez_s[w];
    #pragma unroll
    for (int k = 0; k < Kk; k++) ew[k * 33 + lane] = ez[k];
    __syncwarp();

    // ---- e_zz[m][p][i][j] = Minv[i][j] + ez_i * ez_j (1KB/point, coalesced,
    //      streaming stores: 268 MB write-once traffic bypasses L2 retention) ----
    const int i0 = lane >> 1;
    const int j0 = (lane & 1) * 8;
    const float4 t0 = *(const float4*)&Mi_s[i0][j0];
    const float4 t1 = *(const float4*)&Mi_s[i0][j0 + 4];
    float4* ezz = (float4*)(out + EZZ_OFF + ((size_t)m * Nn + n0 + w * 32) * 256);

    #pragma unroll 2
    for (int p = 0; p < 32; p++) {
        const float ei = ew[i0 * 33 + p];
        float4 e0, e1, v0, v1;
        e0.x = ew[(j0 + 0) * 33 + p]; e0.y = ew[(j0 + 1) * 33 + p];
        e0.z = ew[(j0 + 2) * 33 + p]; e0.w = ew[(j0 + 3) * 33 + p];
        e1.x = ew[(j0 + 4) * 33 + p]; e1.y = ew[(j0 + 5) * 33 + p];
        e1.z = ew[(j0 + 6) * 33 + p]; e1.w = ew[(j0 + 7) * 33 + p];
        v0.x = ei * e0.x + t0.x; v0.y = ei * e0.y + t0.y;
        v0.z = ei * e0.z + t0.z; v0.w = ei * e0.w + t0.w;
        v1.x = ei * e1.x + t1.x; v1.y = ei * e1.y + t1.y;
        v1.z = ei * e1.z + t1.z; v1.w = ei * e1.w + t1.w;
        __stcs(&ezz[(size_t)p * 64 + lane * 2 + 0], v0);
        __stcs(&ezz[(size_t)p * 64 + lane * 2 + 1], v1);
    }
}

// ---------------------------------------------------------------------------
// Kernel 3: responsibilities = softmax over M per point. Thread = one point.
// ---------------------------------------------------------------------------
__global__ __launch_bounds__(256) void resp_kernel(float* __restrict__ out) {
    const int n = blockIdx.x * 256 + threadIdx.x;
    float lp[Mm];
    float mx = -1e30f;
    #pragma unroll
    for (int m = 0; m < Mm; m++) {
        lp[m] = g_logprob[(size_t)m * Nn + n];
        mx = fmaxf(mx, lp[m]);
    }
    float s = 0.0f;
    #pragma unroll
    for (int m = 0; m < Mm; m++) {
        lp[m] = __expf(lp[m] - mx);
        s += lp[m];
    }
    const float inv = 1.0f / s;
    float4* o = (float4*)(out + (size_t)n * Mm);
    #pragma unroll
    for (int r = 0; r < Mm / 4; r++)
        o[r] = make_float4(lp[4 * r] * inv, lp[4 * r + 1] * inv,
                           lp[4 * r + 2] * inv, lp[4 * r + 3] * inv);
}

extern "C" void kernel_launch(void* const* d_in, const int* in_sizes, int n_in,
                              void* d_out, int out_size) {
    // Identify inputs by element count — all five are distinct, so this is
    // robust to any harness input ordering:
    //   X=8192*64=524288, pi=32, mu=32*64=2048, Lambda=32*64*16=32768, Psi=64
    const float* X = 0; const float* pi = 0; const float* mu = 0;
    const float* Lambda = 0; const float* Psi = 0;
    for (int i = 0; i < n_in; i++) {
        switch (in_sizes[i]) {
            case Nn * Dd:        X      = (const float*)d_in[i]; break;
            case Mm:             pi     = (const float*)d_in[i]; break;
            case Mm * Dd:        mu     = (const float*)d_in[i]; break;
            case Mm * Dd * Kk:   Lambda = (const float*)d_in[i]; break;
            case Dd:             Psi    = (const float*)d_in[i]; break;
        }
    }
    float* out = (float*)d_out;

    setup_kernel<<<Mm, 32>>>(pi, Lambda, Psi);
    main_kernel<<<dim3(Nn / 256, Mm), 256>>>(X, mu, Psi, out);
    resp_kernel<<<Nn / 256, 256>>>(out);
}

// round 15
// speedup vs baseline: 1.0566x; 1.0566x over previous
#include <cuda_runtime.h>
#include <cstdint>

#define Mm 32
#define Nn 8192
#define Dd 64
#define Kk 16

// Output packing (concatenated in reference-return order):
//   responsibilities [N, M]            offset 0,        262144 floats
//   e_z              [M, N, K]         offset 262144,   4194304 floats
//   e_zz             [M, N, K, K]      offset 4456448,  67108864 floats
#define EZ_OFF  ((size_t)262144)
#define EZZ_OFF ((size_t)4456448)

// Scratch (static device globals; no allocation)
__device__ float g_beta[Mm][Kk][Dd];    // beta = Minv * Lambda^T * Psi^{-1}  [K,D]
__device__ float g_Mmat[Mm][Kk][Kk];    // M = I + Lambda^T Psi^{-1} Lambda
__device__ float g_Minv[Mm][Kk][Kk];    // M^{-1}  (== term1 exactly)
__device__ float g_cst[Mm];             // log(pi+1e-10) - 0.5*(D log 2pi + logdet Sigma)
__device__ float g_logprob[Mm * Nn];    // [M][N]

// ---------------------------------------------------------------------------
// Kernel 1: per-component setup. 256 threads per component (32 blocks).
// Parallelized vs. R6: M-matrix one entry/thread, coalesced Lambda load,
// warp-parallel logdet reduction. Cholesky remains warp-serial (critical path).
// ---------------------------------------------------------------------------
__global__ __launch_bounds__(256) void setup_kernel(const float* __restrict__ pi,
                                                    const float* __restrict__ Lambda, // [M,D,K]
                                                    const float* __restrict__ Psi) {  // [D]
    const int m = blockIdx.x;
    const int tid = threadIdx.x;
    const int lane = tid & 31;

    __shared__ float Ls[Dd][Kk];     // Lambda_m as [d][k]
    __shared__ float ip[Dd];         // 1/(Psi+1e-6)
    __shared__ float Ms[Kk][Kk];     // M
    __shared__ float Ch[Kk][Kk];     // chol(M), lower
    __shared__ float Mi[Kk][Kk];     // M^{-1}
    __shared__ float s_ldpsi;        // sum log(Psi+1e-6)

    // Coalesced loads: Lambda row-major [d][k] matches Ls layout.
    for (int i = tid; i < Dd * Kk; i += 256)
        ((float*)Ls)[i] = Lambda[(size_t)m * Dd * Kk + i];
    if (tid < Dd)
        ip[tid] = 1.0f / (Psi[tid] + 1e-6f);

    // Warp-parallel logdet(Psi): warp 7 (no dependence on Ls/ip smem).
    if (tid >= 224) {
        float l = logf(Psi[lane] + 1e-6f) + logf(Psi[lane + 32] + 1e-6f);
        #pragma unroll
        for (int o = 16; o > 0; o >>= 1) l += __shfl_xor_sync(0xffffffffu, l, o);
        if (lane == 0) s_ldpsi = l;
    }
    __syncthreads();

    // M = I + Lambda^T Psi^{-1} Lambda : one entry per thread.
    {
        const int k1 = tid >> 4, k2 = tid & 15;
        float s = (k1 == k2) ? 1.0f : 0.0f;
        #pragma unroll 16
        for (int d = 0; d < Dd; d++) s += Ls[d][k1] * Ls[d][k2] * ip[d];
        Ms[k1][k2] = s;
        g_Mmat[m][k1][k2] = s;
    }
    __syncthreads();

    // Warp-cooperative 16x16 Cholesky (warp 0, lanes = rows)
    if (tid < 32) {
        for (int j = 0; j < Kk; j++) {
            float s = 0.0f;
            if (lane >= j && lane < Kk) {
                s = Ms[lane][j];
                for (int k = 0; k < j; k++) s -= Ch[lane][k] * Ch[j][k];
            }
            float diag = __shfl_sync(0xffffffffu, s, j);
            diag = sqrtf(diag);
            if (lane == j) Ch[j][j] = diag;
            else if (lane > j && lane < Kk) Ch[lane][j] = s / diag;
            __syncwarp();
        }

        // logdet(M) via parallel log of Ch diagonal + warp reduce.
        float l = (lane < Kk) ? logf(Ch[lane][lane]) : 0.0f;
        #pragma unroll
        for (int o = 16; o > 0; o >>= 1) l += __shfl_xor_sync(0xffffffffu, l, o);
        if (lane == 0) {
            const float log2pi = 1.8378770664093453f;
            g_cst[m] = logf(pi[m] + 1e-10f)
                     - 0.5f * ((float)Dd * log2pi + s_ldpsi + 2.0f * l);
        }

        // Invert M via two triangular solves; lane c owns column c.
        if (lane < Kk) {
            float w[Kk], z[Kk];
            #pragma unroll
            for (int i = 0; i < Kk; i++) {
                float s = (i == lane) ? 1.0f : 0.0f;
                #pragma unroll
                for (int k = 0; k < Kk; k++) if (k < i) s -= Ch[i][k] * w[k];
                w[i] = s / Ch[i][i];
            }
            #pragma unroll
            for (int i = Kk - 1; i >= 0; i--) {
                float s = w[i];
                #pragma unroll
                for (int k = 0; k < Kk; k++) if (k > i) s -= Ch[k][i] * z[k];
                z[i] = s / Ch[i][i];
            }
            #pragma unroll
            for (int i = 0; i < Kk; i++) {
                Mi[i][lane] = z[i];
                g_Minv[m][i][lane] = z[i];   // term1 == Minv exactly
            }
        }
    }
    __syncthreads();

    // beta[k][d] = (sum_j Minv[k][j] * Lambda[d][j]) * ip[d] : 4 entries/thread.
    for (int e = tid; e < Kk * Dd; e += 256) {
        const int k = e >> 6, d = e & 63;
        float s = 0.0f;
        #pragma unroll
        for (int j = 0; j < Kk; j++) s += Mi[k][j] * Ls[d][j];
        g_beta[m][k][d] = s * ip[d];
    }
}

// ---------------------------------------------------------------------------
// Kernel 2: main E-step. Grid (N/256, M), 256 threads. Thread = one point.
// ---------------------------------------------------------------------------
__global__ __launch_bounds__(256) void main_kernel(const float* __restrict__ X,
                                                   const float* __restrict__ mu,
                                                   const float* __restrict__ Psi,
                                                   float* __restrict__ out) {
    const int m = blockIdx.y;
    const int n0 = blockIdx.x * 256;
    const int tid = threadIdx.x;
    const int n = n0 + tid;
    const int w = tid >> 5, lane = tid & 31;

    __shared__ float beta_s[Kk][Dd];       // 4 KB
    __shared__ float Mm_s[Kk][Kk];         // 1 KB
    __shared__ float Mi_s[Kk][Kk];         // 1 KB
    __shared__ float mu_s[Dd];
    __shared__ float ip_s[Dd];
    __shared__ float ez_s[8][Kk * 33];     // padded stride-33 per warp: ~16.9 KB

    for (int i = tid; i < Kk * Dd; i += 256)
        ((float*)beta_s)[i] = ((const float*)g_beta[m])[i];
    for (int i = tid; i < Kk * Kk; i += 256) {
        ((float*)Mm_s)[i] = ((const float*)g_Mmat[m])[i];
        ((float*)Mi_s)[i] = ((const float*)g_Minv[m])[i];
    }
    if (tid < Dd) {
        mu_s[tid] = mu[m * Dd + tid];
        ip_s[tid] = 1.0f / (Psi[tid] + 1e-6f);
    }
    __syncthreads();

    // ---- e_z = beta * diff ; q = diff^T Psi^{-1} diff ----
    float ez[Kk];
    #pragma unroll
    for (int k = 0; k < Kk; k++) ez[k] = 0.0f;
    float q = 0.0f;

    const float4* xr = (const float4*)(X + (size_t)n * Dd);
    #pragma unroll
    for (int g = 0; g < Dd / 4; g++) {
        const float4 xv = xr[g];
        float4 dv;
        dv.x = xv.x - mu_s[4 * g + 0];
        dv.y = xv.y - mu_s[4 * g + 1];
        dv.z = xv.z - mu_s[4 * g + 2];
        dv.w = xv.w - mu_s[4 * g + 3];
        q += dv.x * dv.x * ip_s[4 * g + 0];
        q += dv.y * dv.y * ip_s[4 * g + 1];
        q += dv.z * dv.z * ip_s[4 * g + 2];
        q += dv.w * dv.w * ip_s[4 * g + 3];
        #pragma unroll
        for (int k = 0; k < Kk; k++) {
            const float4 bv = *(const float4*)&beta_s[k][4 * g];
            ez[k] += dv.x * bv.x + dv.y * bv.y + dv.z * bv.z + dv.w * bv.w;
        }
    }

    // ---- maha = q - ez^T M ez ; log-prob ----
    float quad = 0.0f;
    #pragma unroll
    for (int i = 0; i < Kk; i++) {
        float s = 0.0f;
        #pragma unroll
        for (int j = 0; j < Kk; j++) s += Mm_s[i][j] * ez[j];
        quad += s * ez[i];
    }
    g_logprob[(size_t)m * Nn + n] = g_cst[m] - 0.5f * (q - quad);

    // ---- write e_z directly, streaming (per-thread 64B, warp = 2KB burst) ----
    {
        float4* o = (float4*)(out + EZ_OFF + ((size_t)m * Nn + n) * Kk);
        __stcs(&o[0], make_float4(ez[0], ez[1], ez[2], ez[3]));
        __stcs(&o[1], make_float4(ez[4], ez[5], ez[6], ez[7]));
        __stcs(&o[2], make_float4(ez[8], ez[9], ez[10], ez[11]));
        __stcs(&o[3], make_float4(ez[12], ez[13], ez[14], ez[15]));
    }

    // ---- stage ez into padded smem (transposed) for cooperative e_zz ----
    float* ew = ez_s[w];
    #pragma unroll
    for (int k = 0; k < Kk; k++) ew[k * 33 + lane] = ez[k];
    __syncwarp();

    // ---- e_zz[m][p][i][j] = Minv[i][j] + ez_i * ez_j (1KB/point, coalesced,
    //      streaming stores: 268 MB write-once traffic bypasses L2 retention) ----
    const int i0 = lane >> 1;
    const int j0 = (lane & 1) * 8;
    const float4 t0 = *(const float4*)&Mi_s[i0][j0];
    const float4 t1 = *(const float4*)&Mi_s[i0][j0 + 4];
    float4* ezz = (float4*)(out + EZZ_OFF + ((size_t)m * Nn + n0 + w * 32) * 256);

    #pragma unroll 2
    for (int p = 0; p < 32; p++) {
        const float ei = ew[i0 * 33 + p];
        float4 e0, e1, v0, v1;
        e0.x = ew[(j0 + 0) * 33 + p]; e0.y = ew[(j0 + 1) * 33 + p];
        e0.z = ew[(j0 + 2) * 33 + p]; e0.w = ew[(j0 + 3) * 33 + p];
        e1.x = ew[(j0 + 4) * 33 + p]; e1.y = ew[(j0 + 5) * 33 + p];
        e1.z = ew[(j0 + 6) * 33 + p]; e1.w = ew[(j0 + 7) * 33 + p];
        v0.x = ei * e0.x + t0.x; v0.y = ei * e0.y + t0.y;
        v0.z = ei * e0.z + t0.z; v0.w = ei * e0.w + t0.w;
        v1.x = ei * e1.x + t1.x; v1.y = ei * e1.y + t1.y;
        v1.z = ei * e1.z + t1.z; v1.w = ei * e1.w + t1.w;
        __stcs(&ezz[(size_t)p * 64 + lane * 2 + 0], v0);
        __stcs(&ezz[(size_t)p * 64 + lane * 2 + 1], v1);
    }
}

// ---------------------------------------------------------------------------
// Kernel 3: responsibilities = softmax over M per point. Thread = one point.
// ---------------------------------------------------------------------------
__global__ __launch_bounds__(256) void resp_kernel(float* __restrict__ out) {
    const int n = blockIdx.x * 256 + threadIdx.x;
    float lp[Mm];
    float mx = -1e30f;
    #pragma unroll
    for (int m = 0; m < Mm; m++) {
        lp[m] = g_logprob[(size_t)m * Nn + n];
        mx = fmaxf(mx, lp[m]);
    }
    float s = 0.0f;
    #pragma unroll
    for (int m = 0; m < Mm; m++) {
        lp[m] = __expf(lp[m] - mx);
        s += lp[m];
    }
    const float inv = 1.0f / s;
    float4* o = (float4*)(out + (size_t)n * Mm);
    #pragma unroll
    for (int r = 0; r < Mm / 4; r++)
        o[r] = make_float4(lp[4 * r] * inv, lp[4 * r + 1] * inv,
                           lp[4 * r + 2] * inv, lp[4 * r + 3] * inv);
}

extern "C" void kernel_launch(void* const* d_in, const int* in_sizes, int n_in,
                              void* d_out, int out_size) {
    // Identify inputs by element count — all five are distinct, so this is
    // robust to any harness input ordering:
    //   X=8192*64=524288, pi=32, mu=32*64=2048, Lambda=32*64*16=32768, Psi=64
    const float* X = 0; const float* pi = 0; const float* mu = 0;
    const float* Lambda = 0; const float* Psi = 0;
    for (int i = 0; i < n_in; i++) {
        switch (in_sizes[i]) {
            case Nn * Dd:        X      = (const float*)d_in[i]; break;
            case Mm:             pi     = (const float*)d_in[i]; break;
            case Mm * Dd:        mu     = (const float*)d_in[i]; break;
            case Mm * Dd * Kk:   Lambda = (const float*)d_in[i]; break;
            case Dd:             Psi    = (const float*)d_in[i]; break;
        }
    }
    float* out = (float*)d_out;

    setup_kernel<<<Mm, 256>>>(pi, Lambda, Psi);
    main_kernel<<<dim3(Nn / 256, Mm), 256>>>(X, mu, Psi, out);
    resp_kernel<<<Nn / 256, 256>>>(out);
}

// round 16
// speedup vs baseline: 1.0814x; 1.0235x over previous
#include <cuda_runtime.h>
#include <cstdint>

#define Mm 32
#define Nn 8192
#define Dd 64
#define Kk 16

// Output packing (concatenated in reference-return order):
//   responsibilities [N, M]            offset 0,        262144 floats
//   e_z              [M, N, K]         offset 262144,   4194304 floats
//   e_zz             [M, N, K, K]      offset 4456448,  67108864 floats
#define EZ_OFF  ((size_t)262144)
#define EZZ_OFF ((size_t)4456448)

// Scratch (static device globals; no allocation)
__device__ float g_beta[Mm][Kk][Dd];    // beta = Minv * Lambda^T * Psi^{-1}  [K,D]
__device__ float g_Mmat[Mm][Kk][Kk];    // M = I + Lambda^T Psi^{-1} Lambda
__device__ float g_Minv[Mm][Kk][Kk];    // M^{-1}  (== term1 exactly)
__device__ float g_cst[Mm];             // log(pi+1e-10) - 0.5*(D log 2pi + logdet Sigma)
__device__ float g_logprob[Mm * Nn];    // [M][N]

// ---------------------------------------------------------------------------
// Kernel 1: per-component setup. 256 threads per component (32 blocks).
// R15 rewrite: Gauss-Jordan inversion of M (SPD, no pivoting needed), one
// matrix entry per thread. logdet M = sum of log(pivots). No Cholesky, no
// unrolled triangular solves -> small code body, short serial chain.
// ---------------------------------------------------------------------------
__global__ __launch_bounds__(256) void setup_kernel(const float* __restrict__ pi,
                                                    const float* __restrict__ Lambda, // [M,D,K]
                                                    const float* __restrict__ Psi) {  // [D]
    const int m = blockIdx.x;
    const int tid = threadIdx.x;
    const int lane = tid & 31;
    const int i = tid >> 4, j = tid & 15;   // this thread's matrix entry

    __shared__ float Ls[Dd][Kk];      // Lambda_m as [d][k]
    __shared__ float ip[Dd];          // 1/(Psi+1e-6)
    __shared__ float A[Kk][Kk + 1];   // working copy of M (pad 17)
    __shared__ float Inv[Kk][Kk + 1]; // becomes M^{-1}
    __shared__ float piv[Kk];         // GJ pivots (positive, SPD)
    __shared__ float s_ldpsi;         // sum log(Psi+1e-6)

    // Coalesced loads: Lambda row-major [d][k] matches Ls layout.
    for (int idx = tid; idx < Dd * Kk; idx += 256)
        Ls[idx >> 4][idx & 15] = Lambda[(size_t)m * Dd * Kk + idx];
    if (tid < Dd)
        ip[tid] = 1.0f / (Psi[tid] + 1e-6f);

    // Warp-parallel logdet(Psi): warp 7 (no dependence on Ls/ip smem).
    if (tid >= 224) {
        float l = logf(Psi[lane] + 1e-6f) + logf(Psi[lane + 32] + 1e-6f);
        #pragma unroll
        for (int o = 16; o > 0; o >>= 1) l += __shfl_xor_sync(0xffffffffu, l, o);
        if (lane == 0) s_ldpsi = l;
    }
    __syncthreads();

    // M = I + Lambda^T Psi^{-1} Lambda : one entry per thread.
    {
        float s = (i == j) ? 1.0f : 0.0f;
        for (int d = 0; d < Dd; d++) s += Ls[d][i] * Ls[d][j] * ip[d];
        A[i][j] = s;
        Inv[i][j] = (i == j) ? 1.0f : 0.0f;
        g_Mmat[m][i][j] = s;
    }
    __syncthreads();

    // Gauss-Jordan, no pivoting (SPD, pivots positive). Each thread owns (i,j).
    for (int p = 0; p < Kk; p++) {
        const float pivot = A[p][p];
        const float rp = 1.0f / pivot;
        const float f = A[i][p] * rp;     // row factor for elimination
        const float apj = A[p][j];        // pivot row (unnormalized)
        const float ipj = Inv[p][j];
        if (tid == 0) piv[p] = pivot;
        __syncthreads();                  // all reads done before writes
        if (i == p) {
            A[p][j] = apj * rp;
            Inv[p][j] = ipj * rp;
        } else {
            A[i][j] -= f * apj;
            Inv[i][j] -= f * ipj;
        }
        __syncthreads();                  // writes visible before next reads
    }

    // Inv == M^{-1} == term1. Coalesced store.
    g_Minv[m][i][j] = Inv[i][j];

    // Constant: log(pi+1e-10) - 0.5*(D*log2pi + logdet Psi + logdet M)
    if (tid < 32) {
        float l = (lane < Kk) ? logf(piv[lane]) : 0.0f;
        #pragma unroll
        for (int o = 16; o > 0; o >>= 1) l += __shfl_xor_sync(0xffffffffu, l, o);
        if (lane == 0) {
            const float log2pi = 1.8378770664093453f;
            g_cst[m] = logf(pi[m] + 1e-10f)
                     - 0.5f * ((float)Dd * log2pi + s_ldpsi + l);
        }
    }
    __syncthreads();

    // beta[k][d] = (sum_j Minv[k][j] * Lambda[d][j]) * ip[d] : 4 entries/thread.
    for (int e = tid; e < Kk * Dd; e += 256) {
        const int k = e >> 6, d = e & 63;
        float s = 0.0f;
        #pragma unroll
        for (int jj = 0; jj < Kk; jj++) s += Inv[k][jj] * Ls[d][jj];
        g_beta[m][k][d] = s * ip[d];
    }
}

// ---------------------------------------------------------------------------
// Kernel 2: main E-step. Grid (N/256, M), 256 threads. Thread = one point.
// ---------------------------------------------------------------------------
__global__ __launch_bounds__(256) void main_kernel(const float* __restrict__ X,
                                                   const float* __restrict__ mu,
                                                   const float* __restrict__ Psi,
                                                   float* __restrict__ out) {
    const int m = blockIdx.y;
    const int n0 = blockIdx.x * 256;
    const int tid = threadIdx.x;
    const int n = n0 + tid;
    const int w = tid >> 5, lane = tid & 31;

    __shared__ float beta_s[Kk][Dd];       // 4 KB
    __shared__ float Mm_s[Kk][Kk];         // 1 KB
    __shared__ float Mi_s[Kk][Kk];         // 1 KB
    __shared__ float mu_s[Dd];
    __shared__ float ip_s[Dd];
    __shared__ float ez_s[8][Kk * 33];     // padded stride-33 per warp: ~16.9 KB

    for (int idx = tid; idx < Kk * Dd; idx += 256)
        ((float*)beta_s)[idx] = ((const float*)g_beta[m])[idx];
    for (int idx = tid; idx < Kk * Kk; idx += 256) {
        ((float*)Mm_s)[idx] = ((const float*)g_Mmat[m])[idx];
        ((float*)Mi_s)[idx] = ((const float*)g_Minv[m])[idx];
    }
    if (tid < Dd) {
        mu_s[tid] = mu[m * Dd + tid];
        ip_s[tid] = 1.0f / (Psi[tid] + 1e-6f);
    }
    __syncthreads();

    // ---- e_z = beta * diff ; q = diff^T Psi^{-1} diff ----
    float ez[Kk];
    #pragma unroll
    for (int k = 0; k < Kk; k++) ez[k] = 0.0f;
    float q = 0.0f;

    const float4* xr = (const float4*)(X + (size_t)n * Dd);
    #pragma unroll
    for (int g = 0; g < Dd / 4; g++) {
        const float4 xv = xr[g];
        float4 dv;
        dv.x = xv.x - mu_s[4 * g + 0];
        dv.y = xv.y - mu_s[4 * g + 1];
        dv.z = xv.z - mu_s[4 * g + 2];
        dv.w = xv.w - mu_s[4 * g + 3];
        q += dv.x * dv.x * ip_s[4 * g + 0];
        q += dv.y * dv.y * ip_s[4 * g + 1];
        q += dv.z * dv.z * ip_s[4 * g + 2];
        q += dv.w * dv.w * ip_s[4 * g + 3];
        #pragma unroll
        for (int k = 0; k < Kk; k++) {
            const float4 bv = *(const float4*)&beta_s[k][4 * g];
            ez[k] += dv.x * bv.x + dv.y * bv.y + dv.z * bv.z + dv.w * bv.w;
        }
    }

    // ---- maha = q - ez^T M ez ; log-prob ----
    float quad = 0.0f;
    #pragma unroll
    for (int ii = 0; ii < Kk; ii++) {
        float s = 0.0f;
        #pragma unroll
        for (int jj = 0; jj < Kk; jj++) s += Mm_s[ii][jj] * ez[jj];
        quad += s * ez[ii];
    }
    g_logprob[(size_t)m * Nn + n] = g_cst[m] - 0.5f * (q - quad);

    // ---- write e_z directly, streaming (per-thread 64B, warp = 2KB burst) ----
    {
        float4* o = (float4*)(out + EZ_OFF + ((size_t)m * Nn + n) * Kk);
        __stcs(&o[0], make_float4(ez[0], ez[1], ez[2], ez[3]));
        __stcs(&o[1], make_float4(ez[4], ez[5], ez[6], ez[7]));
        __stcs(&o[2], make_float4(ez[8], ez[9], ez[10], ez[11]));
        __stcs(&o[3], make_float4(ez[12], ez[13], ez[14], ez[15]));
    }

    // ---- stage ez into padded smem (transposed) for cooperative e_zz ----
    float* ew = ez_s[w];
    #pragma unroll
    for (int k = 0; k < Kk; k++) ew[k * 33 + lane] = ez[k];
    __syncwarp();

    // ---- e_zz[m][p][i][j] = Minv[i][j] + ez_i * ez_j (1KB/point, coalesced,
    //      streaming stores: 268 MB write-once traffic bypasses L2 retention) ----
    const int i0 = lane >> 1;
    const int j0 = (lane & 1) * 8;
    const float4 t0 = *(const float4*)&Mi_s[i0][j0];
    const float4 t1 = *(const float4*)&Mi_s[i0][j0 + 4];
    float4* ezz = (float4*)(out + EZZ_OFF + ((size_t)m * Nn + n0 + w * 32) * 256);

    #pragma unroll 2
    for (int p = 0; p < 32; p++) {
        const float ei = ew[i0 * 33 + p];
        float4 e0, e1, v0, v1;
        e0.x = ew[(j0 + 0) * 33 + p]; e0.y = ew[(j0 + 1) * 33 + p];
        e0.z = ew[(j0 + 2) * 33 + p]; e0.w = ew[(j0 + 3) * 33 + p];
        e1.x = ew[(j0 + 4) * 33 + p]; e1.y = ew[(j0 + 5) * 33 + p];
        e1.z = ew[(j0 + 6) * 33 + p]; e1.w = ew[(j0 + 7) * 33 + p];
        v0.x = ei * e0.x + t0.x; v0.y = ei * e0.y + t0.y;
        v0.z = ei * e0.z + t0.z; v0.w = ei * e0.w + t0.w;
        v1.x = ei * e1.x + t1.x; v1.y = ei * e1.y + t1.y;
        v1.z = ei * e1.z + t1.z; v1.w = ei * e1.w + t1.w;
        __stcs(&ezz[(size_t)p * 64 + lane * 2 + 0], v0);
        __stcs(&ezz[(size_t)p * 64 + lane * 2 + 1], v1);
    }
}

// ---------------------------------------------------------------------------
// Kernel 3: responsibilities = softmax over M per point. Thread = one point.
// ---------------------------------------------------------------------------
__global__ __launch_bounds__(256) void resp_kernel(float* __restrict__ out) {
    const int n = blockIdx.x * 256 + threadIdx.x;
    float lp[Mm];
    float mx = -1e30f;
    #pragma unroll
    for (int m = 0; m < Mm; m++) {
        lp[m] = g_logprob[(size_t)m * Nn + n];
        mx = fmaxf(mx, lp[m]);
    }
    float s = 0.0f;
    #pragma unroll
    for (int m = 0; m < Mm; m++) {
        lp[m] = __expf(lp[m] - mx);
        s += lp[m];
    }
    const float inv = 1.0f / s;
    float4* o = (float4*)(out + (size_t)n * Mm);
    #pragma unroll
    for (int r = 0; r < Mm / 4; r++)
        o[r] = make_float4(lp[4 * r] * inv, lp[4 * r + 1] * inv,
                           lp[4 * r + 2] * inv, lp[4 * r + 3] * inv);
}

extern "C" void kernel_launch(void* const* d_in, const int* in_sizes, int n_in,
                              void* d_out, int out_size) {
    // Identify inputs by element count — all five are distinct, so this is
    // robust to any harness input ordering:
    //   X=8192*64=524288, pi=32, mu=32*64=2048, Lambda=32*64*16=32768, Psi=64
    const float* X = 0; const float* pi = 0; const float* mu = 0;
    const float* Lambda = 0; const float* Psi = 0;
    for (int idx = 0; idx < n_in; idx++) {
        switch (in_sizes[idx]) {
            case Nn * Dd:        X      = (const float*)d_in[idx]; break;
            case Mm:             pi     = (const float*)d_in[idx]; break;
            case Mm * Dd:        mu     = (const float*)d_in[idx]; break;
            case Mm * Dd * Kk:   Lambda = (const float*)d_in[idx]; break;
            case Dd:             Psi    = (const float*)d_in[idx]; break;
        }
    }
    float* out = (float*)d_out;

    setup_kernel<<<Mm, 256>>>(pi, Lambda, Psi);
    main_kernel<<<dim3(Nn / 256, Mm), 256>>>(X, mu, Psi, out);
    resp_kernel<<<Nn / 256, 256>>>(out);
}